// round 1
// baseline (speedup 1.0000x reference)
#include <cuda_runtime.h>
#include <math.h>

#define NB     64
#define TT     1024
#define ML     256          // max_lag = T/4
#define PP     (TT - 1)
#define SPLIT  2            // CTAs per batch (lags interleaved by parity)
#define NTHR   256

// Intermediate: log(msd + 1e-8) per (batch, lag)
__device__ float g_logmsd[NB * ML];

// lengths may arrive as int64 or int32 (JAX x64 flag dependent).
// Detect by reading element 0 as int64: valid lengths are in [512,1024];
// an int32-layout read there combines two lengths -> value >= 512*2^32.
__device__ __forceinline__ int get_len(const void* Lp, int b) {
    const long long* L64 = (const long long*)Lp;
    long long v0 = L64[0];
    if (v0 >= 1 && v0 <= (long long)TT) return (int)L64[b];
    return ((const int*)Lp)[b];
}

// ---------------------------------------------------------------------------
// Kernel A: per-(batch,lag) MSD -> log_msd.
// Grid = NB*SPLIT blocks, 256 threads (8 warps). Each block loads its batch's
// trajectory (1024 float2 = 8KB) into SMEM, then each warp owns a set of lags
// (interleaved across blocks & warps so counts n = len - lag stay balanced).
// Lanes stride over positions; warp shfl-reduce.
// ---------------------------------------------------------------------------
__global__ void __launch_bounds__(NTHR)
msd_kernel(const float* __restrict__ traj, const void* __restrict__ lengths)
{
    __shared__ float2 sh[TT];

    const int blk  = blockIdx.x;
    const int b    = blk / SPLIT;
    const int part = blk % SPLIT;

    const float2* row = (const float2*)(traj + (size_t)b * TT * 2);
    #pragma unroll
    for (int i = threadIdx.x; i < TT; i += NTHR) sh[i] = row[i];
    __syncthreads();

    const int len  = get_len(lengths, b);
    const int warp = threadIdx.x >> 5;
    const int lane = threadIdx.x & 31;

    // Block handles lag indices li with li % SPLIT == part; warps stride by 8.
    for (int k = warp; k < ML / SPLIT; k += 8) {
        const int li  = part + SPLIT * k;     // lag index 0..255
        const int lag = li + 1;               // lag 1..256
        int n = len - lag;                    // exact valid count
        if (n > PP) n = PP;

        float acc = 0.0f;
        // unroll-by-2 over positions for MLP
        int p = lane;
        for (; p + 32 < n; p += 64) {
            float2 a0 = sh[p];
            float2 e0 = sh[p + lag];
            float2 a1 = sh[p + 32];
            float2 e1 = sh[p + 32 + lag];
            float dx0 = e0.x - a0.x, dy0 = e0.y - a0.y;
            float dx1 = e1.x - a1.x, dy1 = e1.y - a1.y;
            acc += dx0 * dx0 + dy0 * dy0;
            acc += dx1 * dx1 + dy1 * dy1;
        }
        if (p < n) {
            float2 a = sh[p];
            float2 e = sh[p + lag];
            float dx = e.x - a.x, dy = e.y - a.y;
            acc += dx * dx + dy * dy;
        }

        #pragma unroll
        for (int o = 16; o > 0; o >>= 1)
            acc += __shfl_xor_sync(0xffffffffu, acc, o);

        if (lane == 0) {
            float msd = (n > 0) ? acc / (float)n : 0.0f;
            g_logmsd[b * ML + li] = logf(msd + 1e-8f);
        }
    }
}

// ---------------------------------------------------------------------------
// Kernel B: finish. One block, 256 threads (8 warps). Each warp handles 8
// batches sequentially; lanes hold 8 lags each (256 lags). Computes the
// intercept, squared-error mean per trajectory, then block-reduces to the
// final scalar. No atomics -> fully deterministic.
// ---------------------------------------------------------------------------
__global__ void __launch_bounds__(NTHR)
finish_kernel(const float* __restrict__ alpha_pred,
              const void*  __restrict__ lengths,
              float* __restrict__ out)
{
    __shared__ float pt[NB];

    const int warp = threadIdx.x >> 5;
    const int lane = threadIdx.x & 31;

    // Each lane precomputes log(lag) for its 8 lags.
    float loglag[8];
    #pragma unroll
    for (int j = 0; j < 8; j++)
        loglag[j] = logf((float)(lane + 32 * j + 1));

    for (int b = warp; b < NB; b += 8) {
        const float lenf  = (float)get_len(lengths, b);
        const float alpha = alpha_pred[b];

        float resid[8], mask[8];
        float sr = 0.0f, sm = 0.0f;
        #pragma unroll
        for (int j = 0; j < 8; j++) {
            const int li = lane + 32 * j;
            const float lagf = (float)(li + 1);
            const float lm = g_logmsd[b * ML + li];
            const float m  = (lenf > lagf) ? 1.0f : 0.0f;
            const float r  = lm - alpha * loglag[j];
            resid[j] = r; mask[j] = m;
            sr += r * m;
            sm += m;
        }
        #pragma unroll
        for (int o = 16; o > 0; o >>= 1) {
            sr += __shfl_xor_sync(0xffffffffu, sr, o);
            sm += __shfl_xor_sync(0xffffffffu, sm, o);
        }
        const float denom     = fmaxf(sm, 1.0f);
        const float intercept = sr / denom;

        float se = 0.0f;
        #pragma unroll
        for (int j = 0; j < 8; j++) {
            const float d = intercept - resid[j];
            se += d * d * mask[j];
        }
        #pragma unroll
        for (int o = 16; o > 0; o >>= 1)
            se += __shfl_xor_sync(0xffffffffu, se, o);

        if (lane == 0) pt[b] = se / denom;
    }
    __syncthreads();

    if (warp == 0) {
        float v = pt[lane] + pt[lane + 32];
        #pragma unroll
        for (int o = 16; o > 0; o >>= 1)
            v += __shfl_xor_sync(0xffffffffu, v, o);
        if (lane == 0) out[0] = v / (float)NB;
    }
}

// ---------------------------------------------------------------------------
// Inputs (metadata order): [0] alpha_pred f32[64], [1] trajectory f32[64,1024,2],
// [2] lengths int64/int32[64]. Output: 1 float.
// ---------------------------------------------------------------------------
extern "C" void kernel_launch(void* const* d_in, const int* in_sizes, int n_in,
                              void* d_out, int out_size)
{
    const float* alpha = (const float*)d_in[0];
    const float* traj  = (const float*)d_in[1];
    const void*  lens  = d_in[2];
    float* out = (float*)d_out;

    msd_kernel<<<NB * SPLIT, NTHR>>>(traj, lens);
    finish_kernel<<<1, NTHR>>>(alpha, lens, out);
}

// round 4
// speedup vs baseline: 1.3067x; 1.3067x over previous
#include <cuda_runtime.h>
#include <math.h>

#define NB     64
#define TT     1024
#define ML     256
#define PP     (TT - 1)
#define NTHR   256
#define NBLK   (NB * 2)
#define GL     8            // lags per group
#define NGRP   (ML / GL)    // 32 groups

// Per-CTA partial fit stats: [Sm, S1, S2] in double.
__device__ double g_part[NBLK][3];
__device__ unsigned int g_count;   // zero-init; last block resets each launch

// lengths may arrive as int64 or int32 (JAX x64 flag dependent).
// lengths are in [512,1024]; an int32 layout read as int64 at elem 0 gives >= 2^32.
__device__ __forceinline__ int get_len(const void* Lp, int b) {
    const long long* L64 = (const long long*)Lp;
    long long v0 = L64[0];
    if (v0 >= 1 && v0 <= (long long)TT) return (int)L64[b];
    return ((const int*)Lp)[b];
}

// ---------------------------------------------------------------------------
// Single fused kernel.
// Grid = 128 CTAs (2 per batch, lag-group parity split), 256 threads.
// Each CTA: SMEM-resident trajectory (+ a 1-shifted copy so the 8 lag end
// points load as aligned float4s), register-tiled MSD (warp = 8 consecutive
// lags, lane = 2 consecutive positions -> ~5.5 B/pair of SMEM traffic),
// per-lag fit stats in double, then a last-block deterministic reduction.
// ---------------------------------------------------------------------------
__global__ void __launch_bounds__(NTHR)
fused_kernel(const float* __restrict__ traj,
             const void*  __restrict__ lengths,
             const float* __restrict__ alpha_pred,
             float* __restrict__ out)
{
    __shared__ float4 sh4[TT / 2];    // trajectory, positions 2k,2k+1 per float4
    __shared__ float4 sh14[TT / 2];   // shifted copy: sh1[i] = traj[i+1]
    __shared__ double wpart[8][3];
    __shared__ float  spt[NB];
    __shared__ unsigned int s_last;

    const int blk  = blockIdx.x;
    const int b    = blk >> 1;
    const int part = blk & 1;

    if (threadIdx.x == 0) s_last = 0u;

    float2* shw  = (float2*)sh4;
    float2* sh1w = (float2*)sh14;
    const float2* sh   = (const float2*)sh4;
    const float4* sh1q = (const float4*)sh14;

    const float2* row = (const float2*)(traj + (size_t)b * TT * 2);
    for (int i = threadIdx.x; i < TT; i += NTHR) shw[i] = row[i];
    for (int i = threadIdx.x; i < TT; i += NTHR)
        sh1w[i] = (i < TT - 1) ? row[i + 1] : make_float2(0.f, 0.f);
    __syncthreads();

    const int   len   = get_len(lengths, b);
    const float alpha = alpha_pred[b];
    const int   warp  = threadIdx.x >> 5;
    const int   lane  = threadIdx.x & 31;

    double sm = 0.0, s1 = 0.0, s2 = 0.0;   // meaningful at lane 0 of each warp

    #pragma unroll
    for (int gi = 0; gi < 2; gi++) {
        const int g  = part + 2 * (warp + 8 * gi);   // group id, parity = part
        const int l0 = 1 + GL * g;                   // first lag (always odd)

        int nmin = len - (l0 + GL - 1);
        if (nmin < 0) nmin = 0; if (nmin > PP) nmin = PP;
        int nmax = len - l0;
        if (nmax < 0) nmax = 0; if (nmax > PP) nmax = PP;

        float acc[GL];
        #pragma unroll
        for (int j = 0; j < GL; j++) acc[j] = 0.f;

        // --- main region: all 8 lags valid for every position in the block ---
        const int imax = nmin >> 6;     // 64 positions per warp-iteration
        for (int i = 0; i < imax; i++) {
            const int p  = (i << 6) + (lane << 1);   // even
            float4 aq = sh4[p >> 1];                 // positions p, p+1
            const int k0 = (p + l0 - 1) >> 1;        // l0 odd -> even offset
            float4 e0q = sh1q[k0];                   // p+l0   .. p+l0+1
            float4 e1q = sh1q[k0 + 1];               // p+l0+2 .. p+l0+3
            float4 e2q = sh1q[k0 + 2];
            float4 e3q = sh1q[k0 + 3];               // .. p+l0+7
            float2 e8  = sh[p + l0 + 8];

            float ex[9], ey[9];
            ex[0]=e0q.x; ey[0]=e0q.y;  ex[1]=e0q.z; ey[1]=e0q.w;
            ex[2]=e1q.x; ey[2]=e1q.y;  ex[3]=e1q.z; ey[3]=e1q.w;
            ex[4]=e2q.x; ey[4]=e2q.y;  ex[5]=e2q.z; ey[5]=e2q.w;
            ex[6]=e3q.x; ey[6]=e3q.y;  ex[7]=e3q.z; ey[7]=e3q.w;
            ex[8]=e8.x;  ey[8]=e8.y;

            #pragma unroll
            for (int j = 0; j < GL; j++) {
                float dx0 = ex[j]   - aq.x, dy0 = ey[j]   - aq.y;
                float dx1 = ex[j+1] - aq.z, dy1 = ey[j+1] - aq.w;
                acc[j] += dx0 * dx0 + dy0 * dy0;
                acc[j] += dx1 * dx1 + dy1 * dy1;
            }
        }

        // --- masked tail: remaining positions (< 64 + GL of them) ---
        for (int p = (imax << 6) + lane; p < nmax; p += 32) {
            float2 a = sh[p];
            #pragma unroll
            for (int j = 0; j < GL; j++) {
                int nj = len - (l0 + j);
                if (nj > PP) nj = PP;
                if (p < nj) {
                    float2 e = sh[p + l0 + j];
                    float dx = e.x - a.x, dy = e.y - a.y;
                    acc[j] += dx * dx + dy * dy;
                }
            }
        }

        // --- per-lag warp reduce + fit stats (double) at lane 0 ---
        #pragma unroll
        for (int j = 0; j < GL; j++) {
            #pragma unroll
            for (int o = 16; o > 0; o >>= 1)
                acc[j] += __shfl_xor_sync(0xffffffffu, acc[j], o);
        }
        if (lane == 0) {
            #pragma unroll
            for (int j = 0; j < GL; j++) {
                const int lag = l0 + j;
                int nj = len - lag;
                if (nj > PP) nj = PP;
                float msd = (nj > 0) ? acc[j] / (float)nj : 0.f;
                float r = logf(msd + 1e-8f) - alpha * logf((float)lag);
                if (len > lag) {
                    sm += 1.0;
                    s1 += (double)r;
                    s2 += (double)r * (double)r;
                }
            }
        }
    }

    if (lane == 0) {
        wpart[warp][0] = sm; wpart[warp][1] = s1; wpart[warp][2] = s2;
    }
    __syncthreads();

    if (threadIdx.x == 0) {
        double tm = 0, t1 = 0, t2 = 0;
        #pragma unroll
        for (int w = 0; w < 8; w++) {
            tm += wpart[w][0]; t1 += wpart[w][1]; t2 += wpart[w][2];
        }
        g_part[blk][0] = tm; g_part[blk][1] = t1; g_part[blk][2] = t2;
        __threadfence();
        unsigned int old = atomicAdd(&g_count, 1u);
        s_last = (old == NBLK - 1) ? 1u : 0u;
    }
    __syncthreads();

    if (s_last) {
        __threadfence();
        const int t = threadIdx.x;
        if (t < NB) {
            double Sm = g_part[2*t][0] + g_part[2*t+1][0];
            double S1 = g_part[2*t][1] + g_part[2*t+1][1];
            double S2 = g_part[2*t][2] + g_part[2*t+1][2];
            double denom = (Sm > 1.0) ? Sm : 1.0;
            double I = S1 / denom;
            double pt = (S2 - 2.0 * I * S1 + I * I * Sm) / denom;
            spt[t] = (float)pt;
        }
        __syncthreads();
        if (threadIdx.x < 32) {
            float v = spt[threadIdx.x] + spt[threadIdx.x + 32];
            #pragma unroll
            for (int o = 16; o > 0; o >>= 1)
                v += __shfl_xor_sync(0xffffffffu, v, o);
            if (threadIdx.x == 0) {
                g_count = 0;                 // reset for next graph replay
                __threadfence();
                out[0] = v / (float)NB;
            }
        }
    }
}

// ---------------------------------------------------------------------------
// Inputs: [0] alpha_pred f32[64], [1] trajectory f32[64,1024,2],
// [2] lengths int64/int32[64]. Output: 1 float.
// ---------------------------------------------------------------------------
extern "C" void kernel_launch(void* const* d_in, const int* in_sizes, int n_in,
                              void* d_out, int out_size)
{
    const float* alpha = (const float*)d_in[0];
    const float* traj  = (const float*)d_in[1];
    const void*  lens  = d_in[2];
    float* out = (float*)d_out;

    fused_kernel<<<NBLK, NTHR>>>(traj, lens, alpha, out);
}

// round 6
// speedup vs baseline: 1.3611x; 1.0417x over previous
#include <cuda_runtime.h>
#include <math.h>

#define NB     64
#define TT     1024
#define ML     256
#define PP     (TT - 1)
#define NTHR   128          // 4 warps per CTA
#define CPB    8            // CTAs per batch
#define NBLK   (NB * CPB)   // 512 CTAs -> all co-resident (~4/SM)
#define GL     8            // lags per group
#define NGRP   (ML / GL)    // 32 groups; 4 warps * 8 CTA-parts = 32

// Per-CTA partial fit stats: [Sm, S1, S2] in double.
__device__ double g_part[NBLK][3];
__device__ unsigned int g_count;   // zero-init; last block resets each launch

// lengths may arrive as int64 or int32 (JAX x64 flag dependent).
// lengths are in [512,1024]; an int32 layout read as int64 at elem 0 gives >= 2^32.
__device__ __forceinline__ int get_len(const void* Lp, int b) {
    const long long* L64 = (const long long*)Lp;
    long long v0 = L64[0];
    if (v0 >= 1 && v0 <= (long long)TT) return (int)L64[b];
    return ((const int*)Lp)[b];
}

// ---------------------------------------------------------------------------
// Fused kernel, occupancy-oriented layout:
// 512 CTAs (8 per batch), 128 threads. Each warp owns ONE group of 8
// consecutive lags. SMEM-resident trajectory + a 1-shifted copy so the 8 lag
// endpoints load as aligned float4s (lag-group starts are odd). Register-tiled
// inner loop (lane = 2 consecutive positions -> 16 pairs per 6 LDS).
// Per-lag fit stats in double at lane 0, last-block deterministic reduction.
// ---------------------------------------------------------------------------
__global__ void __launch_bounds__(NTHR)
fused_kernel(const float* __restrict__ traj,
             const void*  __restrict__ lengths,
             const float* __restrict__ alpha_pred,
             float* __restrict__ out)
{
    __shared__ float4 sh4[TT / 2];    // positions 2k,2k+1 per float4
    __shared__ float4 sh14[TT / 2];   // shifted copy: sh1[i] = traj[i+1]
    __shared__ double wpart[4][3];
    __shared__ float  spt[NB];
    __shared__ unsigned int s_last;

    const int blk  = blockIdx.x;
    const int b    = blk >> 3;        // batch
    const int part = blk & 7;         // lag-group slice

    if (threadIdx.x == 0) s_last = 0u;

    float2* shw  = (float2*)sh4;
    float2* sh1w = (float2*)sh14;
    const float2* sh   = (const float2*)sh4;
    const float4* sh1q = (const float4*)sh14;

    const float2* row = (const float2*)(traj + (size_t)b * TT * 2);
    #pragma unroll
    for (int i = threadIdx.x; i < TT; i += NTHR) shw[i] = row[i];
    #pragma unroll
    for (int i = threadIdx.x; i < TT; i += NTHR)
        sh1w[i] = (i < TT - 1) ? row[i + 1] : make_float2(0.f, 0.f);
    __syncthreads();

    const int   len   = get_len(lengths, b);
    const float alpha = alpha_pred[b];
    const int   warp  = threadIdx.x >> 5;
    const int   lane  = threadIdx.x & 31;

    // One group per warp: g in [0,32), interleaved so counts stay balanced.
    const int g  = part + CPB * warp;
    const int l0 = 1 + GL * g;                   // first lag (always odd)

    int nmin = len - (l0 + GL - 1);
    if (nmin < 0) nmin = 0; if (nmin > PP) nmin = PP;
    int nmax = len - l0;
    if (nmax < 0) nmax = 0; if (nmax > PP) nmax = PP;

    float acc[GL];
    #pragma unroll
    for (int j = 0; j < GL; j++) acc[j] = 0.f;

    // --- main region: all 8 lags valid for every position in the block ---
    const int imax = nmin >> 6;     // 64 positions per warp-iteration
    for (int i = 0; i < imax; i++) {
        const int p  = (i << 6) + (lane << 1);   // even
        float4 aq = sh4[p >> 1];                 // positions p, p+1
        const int k0 = (p + l0 - 1) >> 1;        // l0 odd -> aligned
        float4 e0q = sh1q[k0];                   // p+l0   .. p+l0+1
        float4 e1q = sh1q[k0 + 1];
        float4 e2q = sh1q[k0 + 2];
        float4 e3q = sh1q[k0 + 3];               // .. p+l0+7
        float2 e8  = sh[p + l0 + 8];

        float ex[9], ey[9];
        ex[0]=e0q.x; ey[0]=e0q.y;  ex[1]=e0q.z; ey[1]=e0q.w;
        ex[2]=e1q.x; ey[2]=e1q.y;  ex[3]=e1q.z; ey[3]=e1q.w;
        ex[4]=e2q.x; ey[4]=e2q.y;  ex[5]=e2q.z; ey[5]=e2q.w;
        ex[6]=e3q.x; ey[6]=e3q.y;  ex[7]=e3q.z; ey[7]=e3q.w;
        ex[8]=e8.x;  ey[8]=e8.y;

        #pragma unroll
        for (int j = 0; j < GL; j++) {
            float dx0 = ex[j]   - aq.x, dy0 = ey[j]   - aq.y;
            float dx1 = ex[j+1] - aq.z, dy1 = ey[j+1] - aq.w;
            acc[j] += dx0 * dx0 + dy0 * dy0;
            acc[j] += dx1 * dx1 + dy1 * dy1;
        }
    }

    // --- masked tail: remaining positions (< 64 + GL of them) ---
    for (int p = (imax << 6) + lane; p < nmax; p += 32) {
        float2 a = sh[p];
        #pragma unroll
        for (int j = 0; j < GL; j++) {
            int nj = len - (l0 + j);
            if (nj > PP) nj = PP;
            if (p < nj) {
                float2 e = sh[p + l0 + j];
                float dx = e.x - a.x, dy = e.y - a.y;
                acc[j] += dx * dx + dy * dy;
            }
        }
    }

    // --- per-lag warp reduce + fit stats (double) at lane 0 ---
    #pragma unroll
    for (int j = 0; j < GL; j++) {
        #pragma unroll
        for (int o = 16; o > 0; o >>= 1)
            acc[j] += __shfl_xor_sync(0xffffffffu, acc[j], o);
    }
    if (lane == 0) {
        double sm = 0.0, s1 = 0.0, s2 = 0.0;
        #pragma unroll
        for (int j = 0; j < GL; j++) {
            const int lag = l0 + j;
            int nj = len - lag;
            if (nj > PP) nj = PP;
            float msd = (nj > 0) ? acc[j] / (float)nj : 0.f;
            float r = logf(msd + 1e-8f) - alpha * logf((float)lag);
            if (len > lag) {
                sm += 1.0;
                s1 += (double)r;
                s2 += (double)r * (double)r;
            }
        }
        wpart[warp][0] = sm; wpart[warp][1] = s1; wpart[warp][2] = s2;
    }
    __syncthreads();

    if (threadIdx.x == 0) {
        double tm = 0, t1 = 0, t2 = 0;
        #pragma unroll
        for (int w = 0; w < 4; w++) {
            tm += wpart[w][0]; t1 += wpart[w][1]; t2 += wpart[w][2];
        }
        g_part[blk][0] = tm; g_part[blk][1] = t1; g_part[blk][2] = t2;
        __threadfence();
        unsigned int old = atomicAdd(&g_count, 1u);
        s_last = (old == NBLK - 1) ? 1u : 0u;
    }
    __syncthreads();

    if (s_last) {
        __threadfence();
        const int t = threadIdx.x;
        if (t < NB) {
            double Sm = 0, S1 = 0, S2 = 0;
            #pragma unroll
            for (int i = 0; i < CPB; i++) {
                Sm += g_part[CPB * t + i][0];
                S1 += g_part[CPB * t + i][1];
                S2 += g_part[CPB * t + i][2];
            }
            double denom = (Sm > 1.0) ? Sm : 1.0;
            double I = S1 / denom;
            double pt = (S2 - 2.0 * I * S1 + I * I * Sm) / denom;
            spt[t] = (float)pt;
        }
        __syncthreads();
        if (threadIdx.x < 32) {
            float v = spt[threadIdx.x] + spt[threadIdx.x + 32];
            #pragma unroll
            for (int o = 16; o > 0; o >>= 1)
                v += __shfl_xor_sync(0xffffffffu, v, o);
            if (threadIdx.x == 0) {
                g_count = 0;                 // reset for next graph replay
                __threadfence();
                out[0] = v / (float)NB;
            }
        }
    }
}

// ---------------------------------------------------------------------------
// Inputs: [0] alpha_pred f32[64], [1] trajectory f32[64,1024,2],
// [2] lengths int64/int32[64]. Output: 1 float.
// ---------------------------------------------------------------------------
extern "C" void kernel_launch(void* const* d_in, const int* in_sizes, int n_in,
                              void* d_out, int out_size)
{
    const float* alpha = (const float*)d_in[0];
    const float* traj  = (const float*)d_in[1];
    const void*  lens  = d_in[2];
    float* out = (float*)d_out;

    fused_kernel<<<NBLK, NTHR>>>(traj, lens, alpha, out);
}

// round 7
// speedup vs baseline: 1.5223x; 1.1184x over previous
#include <cuda_runtime.h>
#include <math.h>

#define NB     64
#define TT     1024
#define ML     256
#define PP     (TT - 1)
#define NTHR   128          // 4 warps per CTA
#define CPB    16           // CTAs per batch
#define NBLK   (NB * CPB)   // 1024 CTAs, single wave (~7/SM)
#define GL     8            // lags per group; 32 groups x 2 position-halves

// Per-CTA partial fit stats: [Sm, S1, S2] in double.
__device__ double g_part[NBLK][3];
__device__ unsigned int g_count;   // zero-init; last block resets each launch

// lengths may arrive as int64 or int32 (JAX x64 flag dependent).
__device__ __forceinline__ int get_len(const void* Lp, int b) {
    const long long* L64 = (const long long*)Lp;
    long long v0 = L64[0];
    if (v0 >= 1 && v0 <= (long long)TT) return (int)L64[b];
    return ((const int*)Lp)[b];
}

// ---------------------------------------------------------------------------
// 1024 CTAs (16/batch), 128 threads. Each CTA owns 2 adjacent 8-lag groups;
// each group is handled by a PAIR of warps splitting the position range
// (interleaved 64-position blocks; masked tail on half 1). SMEM trajectory +
// 1-shifted copy for aligned float4 endpoint loads. Group halves combine via
// SMEM; per-lag fit stats in double; last-block deterministic reduction.
// ---------------------------------------------------------------------------
__global__ void __launch_bounds__(NTHR)
fused_kernel(const float* __restrict__ traj,
             const void*  __restrict__ lengths,
             const float* __restrict__ alpha_pred,
             float* __restrict__ out)
{
    __shared__ float4 sh4[TT / 2];    // positions 2k,2k+1 per float4
    __shared__ float4 sh14[TT / 2];   // shifted copy: sh1[i] = traj[i+1]
    __shared__ float  sacc[2][2][GL]; // [group-in-CTA][half][lag]
    __shared__ float  spt[NB];
    __shared__ unsigned int s_last;

    const int blk  = blockIdx.x;
    const int b    = blk >> 4;        // batch
    const int part = blk & 15;        // lag-group slice (2 groups per CTA)

    if (threadIdx.x == 0) s_last = 0u;

    float2* shw  = (float2*)sh4;
    float2* sh1w = (float2*)sh14;
    const float2* sh   = (const float2*)sh4;
    const float4* sh1q = (const float4*)sh14;

    const float2* row = (const float2*)(traj + (size_t)b * TT * 2);
    #pragma unroll
    for (int i = threadIdx.x; i < TT; i += NTHR) shw[i] = row[i];
    __syncthreads();
    #pragma unroll
    for (int i = threadIdx.x; i < TT; i += NTHR)
        sh1w[i] = (i < TT - 1) ? sh[i + 1] : make_float2(0.f, 0.f);
    __syncthreads();

    const int   len   = get_len(lengths, b);
    const float alpha = alpha_pred[b];
    const int   warp  = threadIdx.x >> 5;
    const int   lane  = threadIdx.x & 31;

    const int grp  = warp >> 1;                  // 0 or 1 within CTA
    const int half = warp & 1;                   // position half
    const int g    = part * 2 + grp;             // global group id [0,32)
    const int l0   = 1 + GL * g;                 // first lag (odd)

    int nmin = len - (l0 + GL - 1);
    if (nmin < 0) nmin = 0; if (nmin > PP) nmin = PP;
    int nmax = len - l0;
    if (nmax < 0) nmax = 0; if (nmax > PP) nmax = PP;

    float acc[GL];
    #pragma unroll
    for (int j = 0; j < GL; j++) acc[j] = 0.f;

    // --- main region: 64-position blocks, interleaved between the 2 halves ---
    const int imax = nmin >> 6;
    for (int i = half; i < imax; i += 2) {
        const int p  = (i << 6) + (lane << 1);   // even
        float4 aq = sh4[p >> 1];                 // positions p, p+1
        const int k0 = (p + l0 - 1) >> 1;        // l0 odd -> aligned
        float4 e0q = sh1q[k0];
        float4 e1q = sh1q[k0 + 1];
        float4 e2q = sh1q[k0 + 2];
        float4 e3q = sh1q[k0 + 3];
        float2 e8  = sh[p + l0 + 8];

        float ex[9], ey[9];
        ex[0]=e0q.x; ey[0]=e0q.y;  ex[1]=e0q.z; ey[1]=e0q.w;
        ex[2]=e1q.x; ey[2]=e1q.y;  ex[3]=e1q.z; ey[3]=e1q.w;
        ex[4]=e2q.x; ey[4]=e2q.y;  ex[5]=e2q.z; ey[5]=e2q.w;
        ex[6]=e3q.x; ey[6]=e3q.y;  ex[7]=e3q.z; ey[7]=e3q.w;
        ex[8]=e8.x;  ey[8]=e8.y;

        #pragma unroll
        for (int j = 0; j < GL; j++) {
            float dx0 = ex[j]   - aq.x, dy0 = ey[j]   - aq.y;
            float dx1 = ex[j+1] - aq.z, dy1 = ey[j+1] - aq.w;
            acc[j] += dx0 * dx0 + dy0 * dy0;
            acc[j] += dx1 * dx1 + dy1 * dy1;
        }
    }

    // --- masked tail (half 1 only): positions beyond the last full block ---
    if (half == 1) {
        for (int p = (imax << 6) + lane; p < nmax; p += 32) {
            float2 a = sh[p];
            #pragma unroll
            for (int j = 0; j < GL; j++) {
                int nj = len - (l0 + j);
                if (nj > PP) nj = PP;
                if (p < nj) {
                    float2 e = sh[p + l0 + j];
                    float dx = e.x - a.x, dy = e.y - a.y;
                    acc[j] += dx * dx + dy * dy;
                }
            }
        }
    }

    // --- warp reduce, stash per-half sums in SMEM ---
    #pragma unroll
    for (int j = 0; j < GL; j++) {
        #pragma unroll
        for (int o = 16; o > 0; o >>= 1)
            acc[j] += __shfl_xor_sync(0xffffffffu, acc[j], o);
    }
    if (lane == 0) {
        #pragma unroll
        for (int j = 0; j < GL; j++) sacc[grp][half][j] = acc[j];
    }
    __syncthreads();

    // --- epilogue: warp 0 lanes 0..15 each finish one lag; reduce in-warp ---
    if (warp == 0) {
        double sm = 0.0, s1 = 0.0, s2 = 0.0;
        if (lane < 16) {
            const int lg   = lane >> 3;                  // group-in-CTA
            const int jj   = lane & 7;
            const int lag  = 1 + GL * (part * 2 + lg) + jj;
            int nj = len - lag;
            if (nj < 0) nj = 0; if (nj > PP) nj = PP;
            const float tot = sacc[lg][0][jj] + sacc[lg][1][jj];
            const float msd = (nj > 0) ? tot / (float)nj : 0.f;
            const float r = logf(msd + 1e-8f) - alpha * logf((float)lag);
            if (len > lag) {
                sm = 1.0; s1 = (double)r; s2 = (double)r * (double)r;
            }
        }
        #pragma unroll
        for (int o = 16; o > 0; o >>= 1) {
            sm += __shfl_xor_sync(0xffffffffu, sm, o);
            s1 += __shfl_xor_sync(0xffffffffu, s1, o);
            s2 += __shfl_xor_sync(0xffffffffu, s2, o);
        }
        if (lane == 0) {
            g_part[blk][0] = sm; g_part[blk][1] = s1; g_part[blk][2] = s2;
        }
    }
    __syncthreads();

    if (threadIdx.x == 0) {
        __threadfence();
        unsigned int old = atomicAdd(&g_count, 1u);
        s_last = (old == NBLK - 1) ? 1u : 0u;
    }
    __syncthreads();

    if (s_last) {
        __threadfence();
        const int t = threadIdx.x;
        if (t < NB) {
            double Sm = 0, S1 = 0, S2 = 0;
            #pragma unroll
            for (int i = 0; i < CPB; i++) {
                Sm += g_part[CPB * t + i][0];
                S1 += g_part[CPB * t + i][1];
                S2 += g_part[CPB * t + i][2];
            }
            double denom = (Sm > 1.0) ? Sm : 1.0;
            double I = S1 / denom;
            double pt = (S2 - 2.0 * I * S1 + I * I * Sm) / denom;
            spt[t] = (float)pt;
        }
        __syncthreads();
        if (threadIdx.x < 32) {
            float v = spt[threadIdx.x] + spt[threadIdx.x + 32];
            #pragma unroll
            for (int o = 16; o > 0; o >>= 1)
                v += __shfl_xor_sync(0xffffffffu, v, o);
            if (threadIdx.x == 0) {
                g_count = 0;                 // reset for next graph replay
                __threadfence();
                out[0] = v / (float)NB;
            }
        }
    }
}

// ---------------------------------------------------------------------------
// Inputs: [0] alpha_pred f32[64], [1] trajectory f32[64,1024,2],
// [2] lengths int64/int32[64]. Output: 1 float.
// ---------------------------------------------------------------------------
extern "C" void kernel_launch(void* const* d_in, const int* in_sizes, int n_in,
                              void* d_out, int out_size)
{
    const float* alpha = (const float*)d_in[0];
    const float* traj  = (const float*)d_in[1];
    const void*  lens  = d_in[2];
    float* out = (float*)d_out;

    fused_kernel<<<NBLK, NTHR>>>(traj, lens, alpha, out);
}